// round 1
// baseline (speedup 1.0000x reference)
#include <cuda_runtime.h>

#define NPTS 8192
#define KNN  8

// ---------------- scratch (device globals: no allocations allowed) ----------
__device__ int   g_knn[NPTS * KNN];
__device__ float g_x1 [NPTS * 128];   // edgeconv1 output (post-relu)
__device__ float g_A  [NPTS * 128];   // x1 @ (W3a - W3b) + b3
__device__ float g_B  [NPTS * 128];   // x1 @ W3b

#define CSWAP(a,b) { if ((b) < (a)) { unsigned long long _t=(a); (a)=(b); (b)=_t; } }

// ---------------- Kernel 1: KNN (one warp per query) ------------------------
__global__ __launch_bounds__(256) void knn_kernel(const float* __restrict__ pts) {
    const int TS = 2048;
    __shared__ float sx[TS], sy[TS], sz[TS], s2[TS];
    const int lane = threadIdx.x & 31;
    const int warp = threadIdx.x >> 5;
    const int qi = blockIdx.x * 8 + warp;

    const float qx = pts[qi*3+0], qy = pts[qi*3+1], qz = pts[qi*3+2];
    const float q2 = qx*qx + qy*qy + qz*qz;

    unsigned long long k0=~0ULL,k1=~0ULL,k2=~0ULL,k3=~0ULL,
                       k4=~0ULL,k5=~0ULL,k6=~0ULL,k7=~0ULL;

    for (int base = 0; base < NPTS; base += TS) {
        __syncthreads();
        for (int t = threadIdx.x; t < TS; t += 256) {
            float x = pts[(base+t)*3+0];
            float y = pts[(base+t)*3+1];
            float z = pts[(base+t)*3+2];
            sx[t]=x; sy[t]=y; sz[t]=z; s2[t]=x*x+y*y+z*z;
        }
        __syncthreads();
        #pragma unroll 4
        for (int j = lane; j < TS; j += 32) {
            float d = q2 + s2[j] - 2.0f*(qx*sx[j] + qy*sy[j] + qz*sz[j]);
            unsigned int ob = __float_as_uint(d);
            ob ^= ((unsigned int)((int)ob >> 31)) | 0x80000000u;
            unsigned long long key =
                ((unsigned long long)ob << 32) | (unsigned int)(base + j);
            if (key < k7) {
                k7 = key;
                CSWAP(k6,k7); CSWAP(k5,k6); CSWAP(k4,k5); CSWAP(k3,k4);
                CSWAP(k2,k3); CSWAP(k1,k2); CSWAP(k0,k1);
            }
        }
    }
    // warp merge: 8 rounds of warp-min over per-lane sorted heads
    #pragma unroll
    for (int r = 0; r < KNN; r++) {
        unsigned long long m = k0;
        #pragma unroll
        for (int off = 16; off; off >>= 1) {
            unsigned long long o = __shfl_xor_sync(0xFFFFFFFFu, m, off);
            if (o < m) m = o;
        }
        if (k0 == m) { k0=k1; k1=k2; k2=k3; k3=k4; k4=k5; k5=k6; k6=k7; k7=~0ULL; }
        if (lane == 0) g_knn[qi*KNN + r] = (int)(m & 0xFFFFFFFFu);
    }
}

// ---------------- Kernel 2: EdgeConv1 (8 points per block) ------------------
// x1[i] = relu( max_e( relu(e6 @ W1 + b1) @ W2 + b2 ) )
__global__ __launch_bounds__(256) void conv1_kernel(
    const float* __restrict__ pts,
    const float* __restrict__ W1, const float* __restrict__ b1,
    const float* __restrict__ W2, const float* __restrict__ b2)
{
    __shared__ float se[8][8][6];    // edge features
    __shared__ float sh[8][8][64];   // hidden (post-relu)
    const int t  = threadIdx.x;
    const int p0 = blockIdx.x * 8;

    if (t < 64) {
        int p = t >> 3, e = t & 7;
        int i = p0 + p;
        int j = g_knn[i*KNN + e];
        float xi0 = pts[i*3+0], xi1 = pts[i*3+1], xi2 = pts[i*3+2];
        float xj0 = pts[j*3+0], xj1 = pts[j*3+1], xj2 = pts[j*3+2];
        se[p][e][0] = xi0; se[p][e][1] = xi1; se[p][e][2] = xi2;
        se[p][e][3] = xj0 - xi0; se[p][e][4] = xj1 - xi1; se[p][e][5] = xj2 - xi2;
    }
    __syncthreads();

    #pragma unroll
    for (int r = 0; r < 16; r++) {
        int id = t + r*256;            // 0..4095
        int p = id >> 9, e = (id >> 6) & 7, u = id & 63;
        float acc = b1[u];
        #pragma unroll
        for (int f = 0; f < 6; f++) acc += se[p][e][f] * W1[f*64 + u];
        sh[p][e][u] = fmaxf(acc, 0.0f);
    }
    __syncthreads();

    const int p  = t >> 5;             // warp == point
    const int c0 = (t & 31) * 4;       // 4 channels per thread
    float acc[8][4];
    #pragma unroll
    for (int e = 0; e < 8; e++)
        { acc[e][0]=0.f; acc[e][1]=0.f; acc[e][2]=0.f; acc[e][3]=0.f; }

    #pragma unroll 2
    for (int u = 0; u < 64; u++) {
        float4 w = *(const float4*)(W2 + u*128 + c0);
        #pragma unroll
        for (int e = 0; e < 8; e++) {
            float hv = sh[p][e][u];    // broadcast
            acc[e][0] += hv*w.x; acc[e][1] += hv*w.y;
            acc[e][2] += hv*w.z; acc[e][3] += hv*w.w;
        }
    }
    const int i = p0 + p;
    #pragma unroll
    for (int cc = 0; cc < 4; cc++) {
        float m = acc[0][cc];
        #pragma unroll
        for (int e = 1; e < 8; e++) m = fmaxf(m, acc[e][cc]);
        m += b2[c0+cc];
        g_x1[i*128 + c0 + cc] = fmaxf(m, 0.0f);
    }
}

// ---------------- Kernel 3: precompute A, Bv for EdgeConv2 ------------------
// A[i] = x1[i] @ (W3[0:128] - W3[128:256]) + b3 ;  Bv[j] = x1[j] @ W3[128:256]
__global__ __launch_bounds__(128) void pre2_kernel(
    const float* __restrict__ W3, const float* __restrict__ b3)
{
    __shared__ float sx[16][128];
    const int t  = threadIdx.x;
    const int p0 = blockIdx.x * 16;

    #pragma unroll
    for (int r = 0; r < 16; r++) {
        int id = t + r*128; int p = id >> 7; int k = id & 127;
        sx[p][k] = g_x1[(p0+p)*128 + k];
    }
    __syncthreads();

    const int c = t;
    float accA[16], accB[16];
    #pragma unroll
    for (int p = 0; p < 16; p++) { accA[p] = 0.f; accB[p] = 0.f; }

    for (int k = 0; k < 128; k++) {
        float wa = W3[k*128 + c];
        float wb = W3[(k+128)*128 + c];
        float wd = wa - wb;
        #pragma unroll
        for (int p = 0; p < 16; p++) {
            float xv = sx[p][k];       // broadcast
            accA[p] += xv * wd;
            accB[p] += xv * wb;
        }
    }
    float bb = b3[c];
    #pragma unroll
    for (int p = 0; p < 16; p++) {
        g_A[(p0+p)*128 + c] = accA[p] + bb;
        g_B[(p0+p)*128 + c] = accB[p];
    }
}

// ---------------- Kernel 4: EdgeConv2 main (4 points per block) -------------
// out[i][c] = max_e ( relu(A[i] + Bv[j_e]) @ W4 )[c] + b4[c]
__global__ __launch_bounds__(256) void conv2_kernel(
    const float* __restrict__ W4, const float* __restrict__ b4,
    float* __restrict__ out)
{
    __shared__ float sh[4][8][128];
    const int t  = threadIdx.x;
    const int p0 = blockIdx.x * 4;

    #pragma unroll
    for (int r = 0; r < 4; r++) {
        int id = t + r*256;            // float4 index, 0..1023
        int p = id >> 8, e = (id >> 5) & 7, f = id & 31;
        int i = p0 + p;
        int j = g_knn[i*KNN + e];
        float4 a = *(const float4*)(g_A + i*128 + f*4);
        float4 b = *(const float4*)(g_B + j*128 + f*4);
        sh[p][e][f*4+0] = fmaxf(a.x + b.x, 0.0f);
        sh[p][e][f*4+1] = fmaxf(a.y + b.y, 0.0f);
        sh[p][e][f*4+2] = fmaxf(a.z + b.z, 0.0f);
        sh[p][e][f*4+3] = fmaxf(a.w + b.w, 0.0f);
    }
    __syncthreads();

    const int p  = t >> 6;             // 64 threads per point (2 warps, same p)
    const int c0 = (t & 63) * 4;
    float acc[8][4];
    #pragma unroll
    for (int e = 0; e < 8; e++)
        { acc[e][0]=0.f; acc[e][1]=0.f; acc[e][2]=0.f; acc[e][3]=0.f; }

    #pragma unroll 2
    for (int k = 0; k < 128; k++) {
        float4 w = *(const float4*)(W4 + k*256 + c0);
        #pragma unroll
        for (int e = 0; e < 8; e++) {
            float hv = sh[p][e][k];    // broadcast within warp
            acc[e][0] += hv*w.x; acc[e][1] += hv*w.y;
            acc[e][2] += hv*w.z; acc[e][3] += hv*w.w;
        }
    }
    const int i = p0 + p;
    float4 bb = *(const float4*)(b4 + c0);
    float4 o;
    {
        float m0=acc[0][0], m1=acc[0][1], m2=acc[0][2], m3=acc[0][3];
        #pragma unroll
        for (int e = 1; e < 8; e++) {
            m0 = fmaxf(m0, acc[e][0]); m1 = fmaxf(m1, acc[e][1]);
            m2 = fmaxf(m2, acc[e][2]); m3 = fmaxf(m3, acc[e][3]);
        }
        o.x = m0 + bb.x; o.y = m1 + bb.y; o.z = m2 + bb.z; o.w = m3 + bb.w;
    }
    *(float4*)(out + i*256 + c0) = o;
}

// ---------------- launch -----------------------------------------------------
extern "C" void kernel_launch(void* const* d_in, const int* in_sizes, int n_in,
                              void* d_out, int out_size) {
    const float* pts = (const float*)d_in[0];
    const float* W1  = (const float*)d_in[1];
    const float* b1  = (const float*)d_in[2];
    const float* W2  = (const float*)d_in[3];
    const float* b2  = (const float*)d_in[4];
    const float* W3  = (const float*)d_in[5];
    const float* b3  = (const float*)d_in[6];
    const float* W4  = (const float*)d_in[7];
    const float* b4  = (const float*)d_in[8];
    float* out = (float*)d_out;

    knn_kernel  <<<NPTS/8, 256>>>(pts);
    conv1_kernel<<<NPTS/8, 256>>>(pts, W1, b1, W2, b2);
    pre2_kernel <<<NPTS/16, 128>>>(W3, b3);
    conv2_kernel<<<NPTS/4, 256>>>(W4, b4, out);
}

// round 3
// speedup vs baseline: 1.0097x; 1.0097x over previous
#include <cuda_runtime.h>
#include <cuda_bf16.h>
#include <cstdint>

#define NPTS 8192
#define KNN  8

// ---------------- scratch (device globals: no allocations allowed) ----------
__device__ int   g_knn[NPTS * KNN];
__device__ float g_x1 [NPTS * 128];   // edgeconv1 output (post-relu)
__device__ float g_A  [NPTS * 128];   // x1 @ (W3a - W3b) + b3
__device__ float g_B  [NPTS * 128];   // x1 @ W3b
__device__ unsigned short g_w4hi[256 * 128];  // W4^T split-high, [c][k] bf16 bits
__device__ unsigned short g_w4lo[256 * 128];  // W4^T split-low,  [c][k] bf16 bits

#define CSWAP(a,b) { if ((b) < (a)) { unsigned long long _t=(a); (a)=(b); (b)=_t; } }

// ---------------- helpers ----------------------------------------------------
__device__ __forceinline__ uint32_t smem_u32(const void* p) {
    uint32_t a;
    asm("{ .reg .u64 t; cvta.to.shared.u64 t, %1; cvt.u32.u64 %0, t; }"
        : "=r"(a) : "l"(p));
    return a;
}

// round-to-nearest bf16 split: f = hi + lo (both representable as bf16)
__device__ __forceinline__ void bf16_split(float f, uint32_t& hi, uint32_t& lo) {
    uint32_t u = __float_as_uint(f);
    uint32_t hb = (u + 0x7FFFu + ((u >> 16) & 1u)) & 0xFFFF0000u;
    float fl = f - __uint_as_float(hb);
    uint32_t v = __float_as_uint(fl);
    uint32_t lb = (v + 0x7FFFu + ((v >> 16) & 1u));
    hi = hb >> 16;
    lo = lb >> 16;
}

// ---------------- Kernel 1: KNN (one warp per query) ------------------------
__global__ __launch_bounds__(256) void knn_kernel(const float* __restrict__ pts) {
    const int TS = 2048;
    __shared__ float sx[TS], sy[TS], sz[TS], s2[TS];
    const int lane = threadIdx.x & 31;
    const int warp = threadIdx.x >> 5;
    const int qi = blockIdx.x * 8 + warp;

    const float qx = pts[qi*3+0], qy = pts[qi*3+1], qz = pts[qi*3+2];
    const float q2 = qx*qx + qy*qy + qz*qz;

    unsigned long long k0=~0ULL,k1=~0ULL,k2=~0ULL,k3=~0ULL,
                       k4=~0ULL,k5=~0ULL,k6=~0ULL,k7=~0ULL;

    for (int base = 0; base < NPTS; base += TS) {
        __syncthreads();
        for (int t = threadIdx.x; t < TS; t += 256) {
            float x = pts[(base+t)*3+0];
            float y = pts[(base+t)*3+1];
            float z = pts[(base+t)*3+2];
            sx[t]=x; sy[t]=y; sz[t]=z; s2[t]=x*x+y*y+z*z;
        }
        __syncthreads();
        #pragma unroll 4
        for (int j = lane; j < TS; j += 32) {
            float d = q2 + s2[j] - 2.0f*(qx*sx[j] + qy*sy[j] + qz*sz[j]);
            unsigned int ob = __float_as_uint(d);
            ob ^= ((unsigned int)((int)ob >> 31)) | 0x80000000u;
            unsigned long long key =
                ((unsigned long long)ob << 32) | (unsigned int)(base + j);
            if (key < k7) {
                k7 = key;
                CSWAP(k6,k7); CSWAP(k5,k6); CSWAP(k4,k5); CSWAP(k3,k4);
                CSWAP(k2,k3); CSWAP(k1,k2); CSWAP(k0,k1);
            }
        }
    }
    #pragma unroll
    for (int r = 0; r < KNN; r++) {
        unsigned long long m = k0;
        #pragma unroll
        for (int off = 16; off; off >>= 1) {
            unsigned long long o = __shfl_xor_sync(0xFFFFFFFFu, m, off);
            if (o < m) m = o;
        }
        if (k0 == m) { k0=k1; k1=k2; k2=k3; k3=k4; k4=k5; k5=k6; k6=k7; k7=~0ULL; }
        if (lane == 0) g_knn[qi*KNN + r] = (int)(m & 0xFFFFFFFFu);
    }
}

// ---------------- Kernel 2: EdgeConv1 (8 points per block) ------------------
__global__ __launch_bounds__(256) void conv1_kernel(
    const float* __restrict__ pts,
    const float* __restrict__ W1, const float* __restrict__ b1,
    const float* __restrict__ W2, const float* __restrict__ b2)
{
    __shared__ float se[8][8][6];
    __shared__ float sh[8][8][64];
    const int t  = threadIdx.x;
    const int p0 = blockIdx.x * 8;

    if (t < 64) {
        int p = t >> 3, e = t & 7;
        int i = p0 + p;
        int j = g_knn[i*KNN + e];
        float xi0 = pts[i*3+0], xi1 = pts[i*3+1], xi2 = pts[i*3+2];
        float xj0 = pts[j*3+0], xj1 = pts[j*3+1], xj2 = pts[j*3+2];
        se[p][e][0] = xi0; se[p][e][1] = xi1; se[p][e][2] = xi2;
        se[p][e][3] = xj0 - xi0; se[p][e][4] = xj1 - xi1; se[p][e][5] = xj2 - xi2;
    }
    __syncthreads();

    #pragma unroll
    for (int r = 0; r < 16; r++) {
        int id = t + r*256;
        int p = id >> 9, e = (id >> 6) & 7, u = id & 63;
        float acc = b1[u];
        #pragma unroll
        for (int f = 0; f < 6; f++) acc += se[p][e][f] * W1[f*64 + u];
        sh[p][e][u] = fmaxf(acc, 0.0f);
    }
    __syncthreads();

    const int p  = t >> 5;
    const int c0 = (t & 31) * 4;
    float acc[8][4];
    #pragma unroll
    for (int e = 0; e < 8; e++)
        { acc[e][0]=0.f; acc[e][1]=0.f; acc[e][2]=0.f; acc[e][3]=0.f; }

    #pragma unroll 2
    for (int u = 0; u < 64; u++) {
        float4 w = *(const float4*)(W2 + u*128 + c0);
        #pragma unroll
        for (int e = 0; e < 8; e++) {
            float hv = sh[p][e][u];
            acc[e][0] += hv*w.x; acc[e][1] += hv*w.y;
            acc[e][2] += hv*w.z; acc[e][3] += hv*w.w;
        }
    }
    const int i = p0 + p;
    #pragma unroll
    for (int cc = 0; cc < 4; cc++) {
        float m = acc[0][cc];
        #pragma unroll
        for (int e = 1; e < 8; e++) m = fmaxf(m, acc[e][cc]);
        m += b2[c0+cc];
        g_x1[i*128 + c0 + cc] = fmaxf(m, 0.0f);
    }
}

// ---------------- Kernel 3: precompute A, Bv for EdgeConv2 ------------------
__global__ __launch_bounds__(128) void pre2_kernel(
    const float* __restrict__ W3, const float* __restrict__ b3)
{
    __shared__ float sx[16][128];
    const int t  = threadIdx.x;
    const int p0 = blockIdx.x * 16;

    #pragma unroll
    for (int r = 0; r < 16; r++) {
        int id = t + r*128; int p = id >> 7; int k = id & 127;
        sx[p][k] = g_x1[(p0+p)*128 + k];
    }
    __syncthreads();

    const int c = t;
    float accA[16], accB[16];
    #pragma unroll
    for (int p = 0; p < 16; p++) { accA[p] = 0.f; accB[p] = 0.f; }

    for (int k = 0; k < 128; k++) {
        float wa = W3[k*128 + c];
        float wb = W3[(k+128)*128 + c];
        float wd = wa - wb;
        #pragma unroll
        for (int p = 0; p < 16; p++) {
            float xv = sx[p][k];
            accA[p] += xv * wd;
            accB[p] += xv * wb;
        }
    }
    float bb = b3[c];
    #pragma unroll
    for (int p = 0; p < 16; p++) {
        g_A[(p0+p)*128 + c] = accA[p] + bb;
        g_B[(p0+p)*128 + c] = accB[p];
    }
}

// ---------------- Kernel 3b: split + transpose W4 into bf16 hi/lo -----------
__global__ __launch_bounds__(256) void w4split_kernel(const float* __restrict__ W4) {
    int k = blockIdx.x;
    int c = threadIdx.x;
    float w = W4[k*256 + c];
    uint32_t hi, lo;
    bf16_split(w, hi, lo);
    g_w4hi[c*128 + k] = (unsigned short)hi;
    g_w4lo[c*128 + k] = (unsigned short)lo;
}

// ---------------- Kernel 4: EdgeConv2 via mma.sync bf16-split GEMM ----------
// Per CTA: M=128 edge rows (16 points), N=128 channels (blockIdx.y half), K=128.
// SMEM: A hi/lo [128][136] bf16, B hi/lo [128][136] bf16 ([n][k] layout).
// D = Ah@Bh + Ah@Bl + Al@Bh (fp32 accum), epilogue max over 8 edge rows.
#define PADK 136
#define TILE_ELEMS (128 * PADK)
#define CONV2_SMEM (4 * TILE_ELEMS * 2)

__global__ __launch_bounds__(256, 1) void conv2m_kernel(
    const float* __restrict__ b4, float* __restrict__ out)
{
    extern __shared__ __align__(16) char smem[];
    __nv_bfloat16* sAh = (__nv_bfloat16*)smem;
    __nv_bfloat16* sAl = sAh + TILE_ELEMS;
    __nv_bfloat16* sBh = sAl + TILE_ELEMS;
    __nv_bfloat16* sBl = sBh + TILE_ELEMS;

    const int t    = threadIdx.x;
    const int lane = t & 31;
    const int w    = t >> 5;
    const int p0   = blockIdx.x * 16;
    const int c0   = blockIdx.y * 128;

    // ---- build B tiles ([n][k], pre-split in gmem) ----
    {
        const int n = t >> 1, half = t & 1;
        const uint4* hi = (const uint4*)(g_w4hi + (size_t)(c0 + n) * 128 + half * 64);
        const uint4* lo = (const uint4*)(g_w4lo + (size_t)(c0 + n) * 128 + half * 64);
        uint4* dh = (uint4*)(sBh + n * PADK + half * 64);
        uint4* dl = (uint4*)(sBl + n * PADK + half * 64);
        #pragma unroll
        for (int kg = 0; kg < 8; kg++) { dh[kg] = hi[kg]; dl[kg] = lo[kg]; }
    }
    // ---- build A tiles (gather + relu + split) ----
    {
        const int r = t >> 1, half = t & 1;
        const int i = p0 + (r >> 3);
        const int j = g_knn[i * KNN + (r & 7)];
        const float4* pa = (const float4*)(g_A + (size_t)i * 128 + half * 64);
        const float4* pb = (const float4*)(g_B + (size_t)j * 128 + half * 64);
        uint2* dh = (uint2*)(sAh + r * PADK + half * 64);
        uint2* dl = (uint2*)(sAl + r * PADK + half * 64);
        #pragma unroll
        for (int kg = 0; kg < 16; kg++) {
            float4 a = pa[kg];
            float4 b = pb[kg];
            float h0 = fmaxf(a.x + b.x, 0.0f);
            float h1 = fmaxf(a.y + b.y, 0.0f);
            float h2 = fmaxf(a.z + b.z, 0.0f);
            float h3 = fmaxf(a.w + b.w, 0.0f);
            uint32_t h0h,h0l,h1h,h1l,h2h,h2l,h3h,h3l;
            bf16_split(h0, h0h, h0l); bf16_split(h1, h1h, h1l);
            bf16_split(h2, h2h, h2l); bf16_split(h3, h3h, h3l);
            uint2 hw, lw;
            hw.x = h0h | (h1h << 16); hw.y = h2h | (h3h << 16);
            lw.x = h0l | (h1l << 16); lw.y = h2l | (h3l << 16);
            dh[kg] = hw; dl[kg] = lw;
        }
    }
    __syncthreads();

    // ---- MMA mainloop ----
    const int m0 = w * 16;
    float d[16][4];
    #pragma unroll
    for (int nt = 0; nt < 16; nt++)
        { d[nt][0]=0.f; d[nt][1]=0.f; d[nt][2]=0.f; d[nt][3]=0.f; }

    // per-lane ldmatrix offsets (bytes)
    const uint32_t aoff = ((uint32_t)(m0 + (lane & 15)) * PADK +
                           ((lane >> 4) & 1) * 8) * 2;
    const uint32_t boff = ((uint32_t)(lane & 7) * PADK +
                           ((lane >> 3) & 1) * 8) * 2;

    const uint32_t sAh32 = smem_u32(sAh), sAl32 = smem_u32(sAl);
    const uint32_t sBh32 = smem_u32(sBh), sBl32 = smem_u32(sBl);

    #pragma unroll
    for (int pass = 0; pass < 3; pass++) {
        const uint32_t Ab = (pass == 2) ? sAl32 : sAh32;
        const uint32_t Bb = (pass == 1) ? sBl32 : sBh32;
        #pragma unroll
        for (int k16 = 0; k16 < 8; k16++) {
            const uint32_t kb = k16 * 32;   // 16 bf16 = 32 bytes
            uint32_t a0, a1, a2, a3;
            asm volatile(
                "ldmatrix.sync.aligned.m8n8.x4.shared.b16 {%0,%1,%2,%3}, [%4];"
                : "=r"(a0), "=r"(a1), "=r"(a2), "=r"(a3)
                : "r"(Ab + aoff + kb));
            #pragma unroll
            for (int nt = 0; nt < 16; nt++) {
                uint32_t b0, b1;
                asm volatile(
                    "ldmatrix.sync.aligned.m8n8.x2.shared.b16 {%0,%1}, [%2];"
                    : "=r"(b0), "=r"(b1)
                    : "r"(Bb + boff + (uint32_t)nt * (8 * PADK * 2) + kb));
                asm volatile(
                    "mma.sync.aligned.m16n8k16.row.col.f32.bf16.bf16.f32 "
                    "{%0,%1,%2,%3}, {%4,%5,%6,%7}, {%8,%9}, {%0,%1,%2,%3};"
                    : "+f"(d[nt][0]), "+f"(d[nt][1]), "+f"(d[nt][2]), "+f"(d[nt][3])
                    : "r"(a0), "r"(a1), "r"(a2), "r"(a3), "r"(b0), "r"(b1));
            }
        }
    }

    // ---- epilogue: max over 8 edge rows (lane bits [4:2]), write 2 points ----
    // d0,d1: row = lane>>2      (point p0 + w*2,   edge = lane>>2)
    // d2,d3: row = (lane>>2)+8  (point p0 + w*2+1)
    #pragma unroll
    for (int nt = 0; nt < 16; nt++) {
        float v0 = d[nt][0], v1 = d[nt][1], v2 = d[nt][2], v3 = d[nt][3];
        #pragma unroll
        for (int off = 4; off <= 16; off <<= 1) {
            v0 = fmaxf(v0, __shfl_xor_sync(0xFFFFFFFFu, v0, off));
            v1 = fmaxf(v1, __shfl_xor_sync(0xFFFFFFFFu, v1, off));
            v2 = fmaxf(v2, __shfl_xor_sync(0xFFFFFFFFu, v2, off));
            v3 = fmaxf(v3, __shfl_xor_sync(0xFFFFFFFFu, v3, off));
        }
        if (lane < 4) {
            const int c = c0 + nt * 8 + lane * 2;
            const float2 bb = *(const float2*)(b4 + c);
            float2 o0; o0.x = v0 + bb.x; o0.y = v1 + bb.y;
            float2 o1; o1.x = v2 + bb.x; o1.y = v3 + bb.y;
            *(float2*)(out + (size_t)(p0 + w*2    ) * 256 + c) = o0;
            *(float2*)(out + (size_t)(p0 + w*2 + 1) * 256 + c) = o1;
        }
    }
}

// ---------------- launch -----------------------------------------------------
extern "C" void kernel_launch(void* const* d_in, const int* in_sizes, int n_in,
                              void* d_out, int out_size) {
    const float* pts = (const float*)d_in[0];
    const float* W1  = (const float*)d_in[1];
    const float* b1  = (const float*)d_in[2];
    const float* W2  = (const float*)d_in[3];
    const float* b2  = (const float*)d_in[4];
    const float* W3  = (const float*)d_in[5];
    const float* b3  = (const float*)d_in[6];
    const float* W4  = (const float*)d_in[7];
    const float* b4  = (const float*)d_in[8];
    float* out = (float*)d_out;

    cudaFuncSetAttribute(conv2m_kernel,
                         cudaFuncAttributeMaxDynamicSharedMemorySize, CONV2_SMEM);

    knn_kernel    <<<NPTS/8, 256>>>(pts);
    conv1_kernel  <<<NPTS/8, 256>>>(pts, W1, b1, W2, b2);
    w4split_kernel<<<128, 256>>>(W4);
    pre2_kernel   <<<NPTS/16, 128>>>(W3, b3);
    conv2m_kernel <<<dim3(NPTS/16, 2), 256, CONV2_SMEM>>>(b4, out);
}